// round 1
// baseline (speedup 1.0000x reference)
#include <cuda_runtime.h>
#include <math.h>

#define N_TOK  100000
#define C      128
#define CHUNK1 352
#define NB1    ((N_TOK + CHUNK1 - 1) / CHUNK1)   // 285
#define NB3    ((N_TOK + 127) / 128)             // 782

// ---------------- scratch (device globals; no allocations allowed) ----------
__device__ float g_Ut[(size_t)C * N_TOK];        // U transposed: [k][n]
__device__ float g_outbuf[(size_t)C * N_TOK];    // raw logits:   [o][n]
__device__ float g_part[NB1 * C * C];            // GEMM1 partials
__device__ float g_spec[C * C];                  // spec[k][i]
__device__ float g_mixedT[C * C];                // mixed transposed: [k][o]
__device__ float g_pm[NB3 * C];                  // per-block max   [b][o]
__device__ float g_ps[NB3 * C];                  // per-block sumexp[b][o]
__device__ float g_max[C];
__device__ float g_sinv[C];

// ---------------- packed fp32x2 helpers (Blackwell FFMA2) -------------------
__device__ __forceinline__ unsigned long long pack2(float lo, float hi) {
    unsigned long long r;
    asm("mov.b64 %0, {%1, %2};" : "=l"(r) : "f"(lo), "f"(hi));
    return r;
}
__device__ __forceinline__ void unpack2(unsigned long long v, float& lo, float& hi) {
    asm("mov.b64 {%0, %1}, %2;" : "=f"(lo), "=f"(hi) : "l"(v));
}
__device__ __forceinline__ void fma2(unsigned long long& d,
                                     unsigned long long a,
                                     unsigned long long b) {
    asm("fma.rn.f32x2 %0, %1, %2, %0;" : "+l"(d) : "l"(a), "l"(b));
}

// ---------------- 1) transpose U -> g_Ut ------------------------------------
__global__ void k_transpose(const float* __restrict__ U) {
    __shared__ float t[32][33];
    int n0 = blockIdx.x * 32, k0 = blockIdx.y * 32;
    int tx = threadIdx.x, ty = threadIdx.y;          // 32 x 8
#pragma unroll
    for (int r = 0; r < 32; r += 8) {
        int n = n0 + ty + r;
        if (n < N_TOK) t[ty + r][tx] = U[(size_t)n * C + k0 + tx];
    }
    __syncthreads();
#pragma unroll
    for (int r = 0; r < 32; r += 8) {
        int k = k0 + ty + r;
        int n = n0 + tx;
        if (n < N_TOK) g_Ut[(size_t)k * N_TOK + n] = t[tx][ty + r];
    }
}

// ---------------- 2) GEMM1 partials: spec[k][i] += U[n][k]*x[n][i] ----------
__global__ void __launch_bounds__(256) k_gemm1(const float* __restrict__ U,
                                               const float* __restrict__ x) {
    __shared__ float u_s[32][C];
    __shared__ float x_s[32][C];
    int b  = blockIdx.x;
    int n0 = b * CHUNK1;
    int n1 = min(n0 + CHUNK1, N_TOK);
    int tid = threadIdx.x;
    int tx = tid & 15, ty = tid >> 4;

    unsigned long long acc[8][4];
    unsigned long long z = pack2(0.0f, 0.0f);
#pragma unroll
    for (int i = 0; i < 8; i++)
#pragma unroll
        for (int j = 0; j < 4; j++) acc[i][j] = z;

    for (int nb = n0; nb < n1; nb += 32) {
#pragma unroll
        for (int t4 = 0; t4 < 4; t4++) {
            int f  = t4 * 256 + tid;          // float4 idx in 32x32(x4) tile
            int r  = f >> 5, c4 = f & 31;
            int n  = nb + r;
            float4 vu, vx;
            if (n < n1) {
                vu = ((const float4*)(U + (size_t)n * C))[c4];
                vx = ((const float4*)(x + (size_t)n * C))[c4];
            } else {
                vu = make_float4(0.f, 0.f, 0.f, 0.f);
                vx = vu;
            }
            ((float4*)&u_s[r][0])[c4] = vu;
            ((float4*)&x_s[r][0])[c4] = vx;
        }
        __syncthreads();
#pragma unroll 2
        for (int r = 0; r < 32; ++r) {
            float au[8];
            *(float4*)&au[0] = *(const float4*)&u_s[r][8 * ty];
            *(float4*)&au[4] = *(const float4*)&u_s[r][8 * ty + 4];
            unsigned long long bb[4];
            const unsigned long long* bp =
                (const unsigned long long*)&x_s[r][8 * tx];
#pragma unroll
            for (int j = 0; j < 4; j++) bb[j] = bp[j];
#pragma unroll
            for (int ii = 0; ii < 8; ii++) {
                unsigned long long a2 = pack2(au[ii], au[ii]);
#pragma unroll
                for (int j = 0; j < 4; j++) fma2(acc[ii][j], a2, bb[j]);
            }
        }
        __syncthreads();
    }

    float* dst = g_part + (size_t)b * (C * C);
#pragma unroll
    for (int ii = 0; ii < 8; ii++) {
        float v[8];
#pragma unroll
        for (int j = 0; j < 4; j++) unpack2(acc[ii][j], v[2 * j], v[2 * j + 1]);
        float* row = dst + (8 * ty + ii) * C + 8 * tx;
        *(float4*)&row[0] = make_float4(v[0], v[1], v[2], v[3]);
        *(float4*)&row[4] = make_float4(v[4], v[5], v[6], v[7]);
    }
}

// ---------------- 3) reduce partials -> g_spec ------------------------------
__global__ void k_reduce_spec() {
    int j = blockIdx.x * 256 + threadIdx.x;   // 64 * 256 = 16384
    float s = 0.f;
    for (int b = 0; b < NB1; b++) s += g_part[b * (C * C) + j];
    g_spec[j] = s;
}

// ---------------- 4) mixed: mixedT[k][o] = dot(coeffs[o][k][:], spec[k][:]) -
__global__ void k_mixed(const float* __restrict__ coeffs) {
    int t = threadIdx.x;          // k
    int o = blockIdx.x;
    const float4* cf4 = (const float4*)(coeffs + ((size_t)o * C + t) * C);
    const float4* sp4 = (const float4*)(g_spec + t * C);
    float s = 0.f;
#pragma unroll 8
    for (int i = 0; i < C / 4; i++) {
        float4 a = cf4[i], b = sp4[i];
        s += a.x * b.x + a.y * b.y + a.z * b.z + a.w * b.w;
    }
    g_mixedT[t * C + o] = s;
}

// ---------------- 5) GEMM2 + online softmax partials ------------------------
// out[o][n] = sum_k mixedT[k][o] * Ut[k][n]; tile 128o x 128n per block.
__global__ void __launch_bounds__(256) k_gemm3() {
    extern __shared__ float sh[];
    float* m_s = sh;              // [k][o] 128x128
    float* u_s = sh + C * C;      // [k][n] 128x128
    int b  = blockIdx.x;
    int n0 = b * 128;
    int tid = threadIdx.x;
    int tx = tid & 15, ty = tid >> 4;
    int nvalid = min(128, N_TOK - n0);

#pragma unroll
    for (int t4 = 0; t4 < 16; t4++) {
        int f = t4 * 256 + tid;                 // float4 idx over 4096
        ((float4*)m_s)[f] = ((const float4*)g_mixedT)[f];
        int k = f >> 5, c4 = f & 31;
        int n = n0 + c4 * 4;
        float4 v = make_float4(0.f, 0.f, 0.f, 0.f);
        if (n < N_TOK)
            v = ((const float4*)(g_Ut + (size_t)k * N_TOK + n0))[c4];
        ((float4*)u_s)[f] = v;
    }
    __syncthreads();

    unsigned long long acc[8][4];
    unsigned long long z = pack2(0.0f, 0.0f);
#pragma unroll
    for (int i = 0; i < 8; i++)
#pragma unroll
        for (int j = 0; j < 4; j++) acc[i][j] = z;

#pragma unroll 4
    for (int k = 0; k < C; k++) {
        float am[8];
        *(float4*)&am[0] = *(const float4*)&m_s[k * C + 8 * ty];
        *(float4*)&am[4] = *(const float4*)&m_s[k * C + 8 * ty + 4];
        unsigned long long bb[4];
        const unsigned long long* bp =
            (const unsigned long long*)&u_s[k * C + 8 * tx];
#pragma unroll
        for (int j = 0; j < 4; j++) bb[j] = bp[j];
#pragma unroll
        for (int ii = 0; ii < 8; ii++) {
            unsigned long long a2 = pack2(am[ii], am[ii]);
#pragma unroll
            for (int j = 0; j < 4; j++) fma2(acc[ii][j], a2, bb[j]);
        }
    }

    float lm[8], ls[8];
#pragma unroll
    for (int ii = 0; ii < 8; ii++) {
        float v[8];
#pragma unroll
        for (int j = 0; j < 4; j++) unpack2(acc[ii][j], v[2 * j], v[2 * j + 1]);
        int o = 8 * ty + ii;
        // store raw logits (guarded)
        if (8 * tx + 7 < nvalid) {
            float* row = g_outbuf + (size_t)o * N_TOK + n0 + 8 * tx;
            *(float4*)&row[0] = make_float4(v[0], v[1], v[2], v[3]);
            *(float4*)&row[4] = make_float4(v[4], v[5], v[6], v[7]);
        } else {
#pragma unroll
            for (int j = 0; j < 8; j++)
                if (8 * tx + j < nvalid)
                    g_outbuf[(size_t)o * N_TOK + n0 + 8 * tx + j] = v[j];
        }
        float m = -INFINITY, s = 0.f;
#pragma unroll
        for (int j = 0; j < 8; j++)
            if (8 * tx + j < nvalid) m = fmaxf(m, v[j]);
        if (m > -INFINITY) {
#pragma unroll
            for (int j = 0; j < 8; j++)
                if (8 * tx + j < nvalid) s += expf(v[j] - m);
        }
        lm[ii] = m; ls[ii] = s;
    }

    __syncthreads();                 // done with u_s -> reuse as reduction buf
    float* red = u_s;                // [o][32]: m at +tx, s at +16+tx
#pragma unroll
    for (int ii = 0; ii < 8; ii++) {
        int o = 8 * ty + ii;
        red[o * 32 + tx]       = lm[ii];
        red[o * 32 + 16 + tx]  = ls[ii];
    }
    __syncthreads();
    if (tid < C) {
        int o = tid;
        float M = -INFINITY;
#pragma unroll
        for (int t = 0; t < 16; t++) M = fmaxf(M, red[o * 32 + t]);
        float S = 0.f;
        if (M > -INFINITY) {
#pragma unroll
            for (int t = 0; t < 16; t++) {
                float mm = red[o * 32 + t];
                if (mm > -INFINITY) S += red[o * 32 + 16 + t] * expf(mm - M);
            }
        }
        g_pm[b * C + o] = M;
        g_ps[b * C + o] = S;
    }
}

// ---------------- 6) combine softmax partials -------------------------------
__global__ void k_softmax_reduce() {
    int o = threadIdx.x;            // 128 threads
    float M = -INFINITY, S = 0.f;
    for (int b = 0; b < NB3; b++) {
        float m = g_pm[b * C + o];
        float s = g_ps[b * C + o];
        if (m > M) {
            S = S * expf(M - m) + s;   // expf(-inf - finite) = 0 first iter
            M = m;
        } else if (s > 0.f) {
            S += s * expf(m - M);
        }
    }
    g_max[o]  = M;
    g_sinv[o] = 1.0f / S;
}

// ---------------- 7) final: transpose + exp + normalize ---------------------
__global__ void k_final(float* __restrict__ out) {
    __shared__ float t[32][33];
    int n0 = blockIdx.x * 32, o0 = blockIdx.y * 32;
    int tx = threadIdx.x, ty = threadIdx.y;    // 32 x 8
#pragma unroll
    for (int r = 0; r < 32; r += 8) {
        int n = n0 + tx;
        int o = o0 + ty + r;
        if (n < N_TOK) t[ty + r][tx] = g_outbuf[(size_t)o * N_TOK + n];
    }
    __syncthreads();
    float M = g_max[o0 + tx];
    float I = g_sinv[o0 + tx];
#pragma unroll
    for (int r = 0; r < 32; r += 8) {
        int n = n0 + ty + r;
        if (n < N_TOK)
            out[(size_t)n * C + o0 + tx] = expf(t[tx][ty + r] - M) * I;
    }
}

// ---------------- launcher ---------------------------------------------------
extern "C" void kernel_launch(void* const* d_in, const int* in_sizes, int n_in,
                              void* d_out, int out_size) {
    const float* x      = (const float*)d_in[0];
    const float* U      = (const float*)d_in[1];
    const float* coeffs = (const float*)d_in[2];
    float* out = (float*)d_out;

    cudaFuncSetAttribute(k_gemm3, cudaFuncAttributeMaxDynamicSharedMemorySize,
                         2 * C * C * (int)sizeof(float));

    dim3 tgrid((N_TOK + 31) / 32, C / 32);
    dim3 tblk(32, 8);
    k_transpose<<<tgrid, tblk>>>(U);
    k_gemm1<<<NB1, 256>>>(U, x);
    k_reduce_spec<<<64, 256>>>();
    k_mixed<<<C, C>>>(coeffs);
    k_gemm3<<<NB3, 256, 2 * C * C * (int)sizeof(float)>>>();
    k_softmax_reduce<<<1, C>>>();
    k_final<<<tgrid, tblk>>>(out);
}

// round 2
// speedup vs baseline: 1.7565x; 1.7565x over previous
#include <cuda_runtime.h>
#include <math.h>

#define N_TOK  100000
#define C      128
#define CHUNK1 352
#define NB1    ((N_TOK + CHUNK1 - 1) / CHUNK1)   // 285
#define NB3    ((N_TOK + 127) / 128)             // 782

typedef unsigned long long ull;

// ---------------- scratch (device globals; no allocations allowed) ----------
__device__ float g_part[NB1 * C * C];            // GEMM1 partials
__device__ float g_spec8[8 * C * C];             // stage-1 reduced spec
__device__ float g_spec[C * C];                  // spec[k][i]
__device__ float g_mixedT[C * C];                // mixed transposed: [k][o]
__device__ float g_pm[NB3 * C];                  // per-block max   [b][o]
__device__ float g_ps[NB3 * C];                  // per-block sumexp[b][o]
__device__ float g_max[C];
__device__ float g_sinv[C];

// ---------------- packed fp32x2 helpers (Blackwell FFMA2) -------------------
__device__ __forceinline__ ull pack2(float lo, float hi) {
    ull r;
    asm("mov.b64 %0, {%1, %2};" : "=l"(r) : "f"(lo), "f"(hi));
    return r;
}
__device__ __forceinline__ void unpack2(ull v, float& lo, float& hi) {
    asm("mov.b64 {%0, %1}, %2;" : "=f"(lo), "=f"(hi) : "l"(v));
}
__device__ __forceinline__ void fma2(ull& d, ull a, ull b) {
    asm("fma.rn.f32x2 %0, %1, %2, %0;" : "+l"(d) : "l"(a), "l"(b));
}

// online-softmax pair combine
__device__ __forceinline__ void comb(float& m, float& s, float m2, float s2) {
    float M = fmaxf(m, m2);
    float S = 0.f;
    if (m  > -INFINITY) S += s  * __expf(m  - M);
    if (m2 > -INFINITY) S += s2 * __expf(m2 - M);
    m = M; s = S;
}

// ---------------- 1) GEMM1 partials: spec[k][i] += U[n][k]*x[n][i] ----------
__global__ void __launch_bounds__(256) k_gemm1(const float* __restrict__ U,
                                               const float* __restrict__ x) {
    __shared__ float u_s[32][C];
    __shared__ float x_s[32][C];
    int b  = blockIdx.x;
    int n0 = b * CHUNK1;
    int n1 = min(n0 + CHUNK1, N_TOK);
    int tid = threadIdx.x;
    int tx = tid & 15, ty = tid >> 4;

    ull acc[8][4];
    ull z = pack2(0.0f, 0.0f);
#pragma unroll
    for (int i = 0; i < 8; i++)
#pragma unroll
        for (int j = 0; j < 4; j++) acc[i][j] = z;

    for (int nb = n0; nb < n1; nb += 32) {
#pragma unroll
        for (int t4 = 0; t4 < 4; t4++) {
            int f  = t4 * 256 + tid;
            int r  = f >> 5, c4 = f & 31;
            int n  = nb + r;
            float4 vu, vx;
            if (n < n1) {
                vu = ((const float4*)(U + (size_t)n * C))[c4];
                vx = ((const float4*)(x + (size_t)n * C))[c4];
            } else {
                vu = make_float4(0.f, 0.f, 0.f, 0.f);
                vx = vu;
            }
            ((float4*)&u_s[r][0])[c4] = vu;
            ((float4*)&x_s[r][0])[c4] = vx;
        }
        __syncthreads();
#pragma unroll 2
        for (int r = 0; r < 32; ++r) {
            float au[8];
            *(float4*)&au[0] = *(const float4*)&u_s[r][8 * ty];
            *(float4*)&au[4] = *(const float4*)&u_s[r][8 * ty + 4];
            ull bb[4];
            const ull* bp = (const ull*)&x_s[r][8 * tx];
#pragma unroll
            for (int j = 0; j < 4; j++) bb[j] = bp[j];
#pragma unroll
            for (int ii = 0; ii < 8; ii++) {
                ull a2 = pack2(au[ii], au[ii]);
#pragma unroll
                for (int j = 0; j < 4; j++) fma2(acc[ii][j], a2, bb[j]);
            }
        }
        __syncthreads();
    }

    float* dst = g_part + (size_t)b * (C * C);
#pragma unroll
    for (int ii = 0; ii < 8; ii++) {
        float v[8];
#pragma unroll
        for (int j = 0; j < 4; j++) unpack2(acc[ii][j], v[2 * j], v[2 * j + 1]);
        float* row = dst + (8 * ty + ii) * C + 8 * tx;
        *(float4*)&row[0] = make_float4(v[0], v[1], v[2], v[3]);
        *(float4*)&row[4] = make_float4(v[4], v[5], v[6], v[7]);
    }
}

// ---------------- 2) reduce partials (2-stage) ------------------------------
__global__ void k_reduce8() {
    int y = blockIdx.y;
    int j = blockIdx.x * 256 + threadIdx.x;
    int b0 = y * 36, b1 = min(b0 + 36, NB1);
    float s = 0.f;
    for (int b = b0; b < b1; b++) s += g_part[b * (C * C) + j];
    g_spec8[y * (C * C) + j] = s;
}
__global__ void k_sumspec() {
    int j = blockIdx.x * 256 + threadIdx.x;
    float s = 0.f;
#pragma unroll
    for (int y = 0; y < 8; y++) s += g_spec8[y * (C * C) + j];
    g_spec[j] = s;
}

// ---------------- 3) mixed: one warp per (o,k) ------------------------------
__global__ void __launch_bounds__(256) k_mixed_w(const float* __restrict__ coeffs) {
    int warp = (blockIdx.x * 256 + threadIdx.x) >> 5;
    int lane = threadIdx.x & 31;
    int o = warp >> 7, k = warp & 127;
    const float4* cf = (const float4*)(coeffs + (((size_t)o * C + k) << 7));
    const float4* sp = (const float4*)(g_spec + (k << 7));
    float4 a = cf[lane], bv = sp[lane];
    float s = a.x * bv.x + a.y * bv.y + a.z * bv.z + a.w * bv.w;
#pragma unroll
    for (int off = 16; off; off >>= 1) s += __shfl_xor_sync(0xffffffffu, s, off);
    if (lane == 0) g_mixedT[k * C + o] = s;
}

// ---------------- 4) GEMM2 + logit store [n][o] + softmax partials ----------
#define UTP 132    // padded row stride (floats) for transposed U tile
__global__ void __launch_bounds__(512) k_gemm3b(const float* __restrict__ U,
                                                float* __restrict__ out) {
    extern __shared__ float sh[];
    float* m_s = sh;               // [k][o] 128x128
    float* u_t = sh + C * C;       // [k][n] 128xUTP
    int b  = blockIdx.x;
    int n0 = b << 7;
    int tid = threadIdx.x;
    int tx = tid & 15, ty = tid >> 4;
    int nvalid = min(128, N_TOK - n0);

#pragma unroll
    for (int i = 0; i < 8; i++) {
        int f = i * 512 + tid;     // float4 index over 4096
        ((float4*)m_s)[f] = ((const float4*)g_mixedT)[f];
    }
#pragma unroll
    for (int i = 0; i < 8; i++) {
        int f = i * 512 + tid;
        int r = f >> 5, c4 = f & 31;
        float4 v = make_float4(0.f, 0.f, 0.f, 0.f);
        if (r < nvalid)
            v = ((const float4*)(U + (size_t)(n0 + r) * C))[c4];
        u_t[(4 * c4 + 0) * UTP + r] = v.x;
        u_t[(4 * c4 + 1) * UTP + r] = v.y;
        u_t[(4 * c4 + 2) * UTP + r] = v.z;
        u_t[(4 * c4 + 3) * UTP + r] = v.w;
    }
    __syncthreads();

    ull acc[4][4];
    ull z = pack2(0.f, 0.f);
#pragma unroll
    for (int i = 0; i < 4; i++)
#pragma unroll
        for (int j = 0; j < 4; j++) acc[i][j] = z;

#pragma unroll 8
    for (int k = 0; k < C; k++) {
        float4 am = *(const float4*)&m_s[k * C + 4 * ty];
        const ull* bp = (const ull*)&u_t[k * UTP + 8 * tx];
        ull b0 = bp[0], b1 = bp[1], b2 = bp[2], b3 = bp[3];
        ull a0 = pack2(am.x, am.x);
        ull a1 = pack2(am.y, am.y);
        ull a2 = pack2(am.z, am.z);
        ull a3 = pack2(am.w, am.w);
        fma2(acc[0][0], a0, b0); fma2(acc[0][1], a0, b1);
        fma2(acc[0][2], a0, b2); fma2(acc[0][3], a0, b3);
        fma2(acc[1][0], a1, b0); fma2(acc[1][1], a1, b1);
        fma2(acc[1][2], a1, b2); fma2(acc[1][3], a1, b3);
        fma2(acc[2][0], a2, b0); fma2(acc[2][1], a2, b1);
        fma2(acc[2][2], a2, b2); fma2(acc[2][3], a2, b3);
        fma2(acc[3][0], a3, b0); fma2(acc[3][1], a3, b1);
        fma2(acc[3][2], a3, b2); fma2(acc[3][3], a3, b3);
    }

    float v[4][8];
#pragma unroll
    for (int ii = 0; ii < 4; ii++)
#pragma unroll
        for (int j = 0; j < 4; j++)
            unpack2(acc[ii][j], v[ii][2 * j], v[ii][2 * j + 1]);

    // store logits transposed: out[n][o] (float4 over 4 consecutive o's)
#pragma unroll
    for (int j = 0; j < 8; j++) {
        int n = n0 + 8 * tx + j;
        if (n < N_TOK)
            *(float4*)&out[(size_t)n * C + 4 * ty] =
                make_float4(v[0][j], v[1][j], v[2][j], v[3][j]);
    }

    // per-thread softmax partials over this thread's 8 n's, 4 o's
    float lm[4], ls[4];
#pragma unroll
    for (int ii = 0; ii < 4; ii++) {
        float m = -INFINITY;
#pragma unroll
        for (int j = 0; j < 8; j++)
            if (8 * tx + j < nvalid) m = fmaxf(m, v[ii][j]);
        float s = 0.f;
        if (m > -INFINITY) {
#pragma unroll
            for (int j = 0; j < 8; j++)
                if (8 * tx + j < nvalid) s += __expf(v[ii][j] - m);
        }
        lm[ii] = m; ls[ii] = s;
    }
    // reduce across the 16 tx lanes (half-warp; ty fixed within half-warp)
#pragma unroll
    for (int off = 8; off; off >>= 1) {
#pragma unroll
        for (int ii = 0; ii < 4; ii++) {
            float m2 = __shfl_xor_sync(0xffffffffu, lm[ii], off);
            float s2 = __shfl_xor_sync(0xffffffffu, ls[ii], off);
            comb(lm[ii], ls[ii], m2, s2);
        }
    }
    if (tx == 0) {
#pragma unroll
        for (int ii = 0; ii < 4; ii++) {
            g_pm[b * C + 4 * ty + ii] = lm[ii];
            g_ps[b * C + 4 * ty + ii] = ls[ii];
        }
    }
}

// ---------------- 5) combine softmax partials (parallel) --------------------
__global__ void k_softmax_par() {
    int o = blockIdx.x;
    float M = -INFINITY, S = 0.f;
    for (int b = threadIdx.x; b < NB3; b += 256)
        comb(M, S, g_pm[b * C + o], g_ps[b * C + o]);
    // warp reduce
#pragma unroll
    for (int off = 16; off; off >>= 1) {
        float m2 = __shfl_xor_sync(0xffffffffu, M, off);
        float s2 = __shfl_xor_sync(0xffffffffu, S, off);
        comb(M, S, m2, s2);
    }
    __shared__ float sm[8], ss[8];
    int w = threadIdx.x >> 5, lane = threadIdx.x & 31;
    if (lane == 0) { sm[w] = M; ss[w] = S; }
    __syncthreads();
    if (threadIdx.x == 0) {
#pragma unroll
        for (int i = 1; i < 8; i++) comb(sm[0], ss[0], sm[i], ss[i]);
        g_max[o]  = sm[0];
        g_sinv[o] = 1.0f / ss[0];
    }
}

// ---------------- 6) final: in-place exp + normalize ------------------------
__global__ void k_final2(float* __restrict__ out) {
    int f = blockIdx.x * 256 + threadIdx.x;   // float4 index, 3.2M total
    float4 v = ((const float4*)out)[f];
    int og = f & 31;                           // float4 idx within 128-o row
    float4 M = ((const float4*)g_max)[og];
    float4 I = ((const float4*)g_sinv)[og];
    v.x = expf(v.x - M.x) * I.x;
    v.y = expf(v.y - M.y) * I.y;
    v.z = expf(v.z - M.z) * I.z;
    v.w = expf(v.w - M.w) * I.w;
    ((float4*)out)[f] = v;
}

// ---------------- launcher ---------------------------------------------------
extern "C" void kernel_launch(void* const* d_in, const int* in_sizes, int n_in,
                              void* d_out, int out_size) {
    const float* x      = (const float*)d_in[0];
    const float* U      = (const float*)d_in[1];
    const float* coeffs = (const float*)d_in[2];
    float* out = (float*)d_out;

    int smem3 = (C * C + C * UTP) * (int)sizeof(float);   // 133120
    cudaFuncSetAttribute(k_gemm3b, cudaFuncAttributeMaxDynamicSharedMemorySize,
                         smem3);

    k_gemm1<<<NB1, 256>>>(U, x);
    dim3 rg(64, 8);
    k_reduce8<<<rg, 256>>>();
    k_sumspec<<<64, 256>>>();
    k_mixed_w<<<2048, 256>>>(coeffs);
    k_gemm3b<<<NB3, 512, smem3>>>(U, out);
    k_softmax_par<<<C, 256>>>();
    k_final2<<<(N_TOK * C / 4) / 256, 256>>>(out);
}

// round 4
// speedup vs baseline: 2.5880x; 1.4734x over previous
#include <cuda_runtime.h>
#include <math.h>

#define N_TOK  100000
#define C      128
#define CHUNK1 352
#define NB1    ((N_TOK + CHUNK1 - 1) / CHUNK1)   // 285
#define NT3    64                                 // n-tile of GEMM2
#define NB3    ((N_TOK + NT3 - 1) / NT3)          // 1563

typedef unsigned long long ull;

// ---------------- scratch (device globals) ----------------------------------
__device__ float g_part[NB1 * C * C];            // GEMM1 partials
__device__ float g_spec[C * C];                  // spec[k][i]
__device__ float g_mixedT[C * C];                // mixed transposed: [k][o]
__device__ float g_pm[C * NB3];                  // per-block max   [o][b]
__device__ float g_ps[C * NB3];                  // per-block sumexp[o][b]
__device__ float g_max[C];
__device__ float g_sinv[C];

// ---------------- packed fp32x2 helpers (Blackwell FFMA2) -------------------
__device__ __forceinline__ ull pack2(float lo, float hi) {
    ull r;
    asm("mov.b64 %0, {%1, %2};" : "=l"(r) : "f"(lo), "f"(hi));
    return r;
}
__device__ __forceinline__ void unpack2(ull v, float& lo, float& hi) {
    asm("mov.b64 {%0, %1}, %2;" : "=f"(lo), "=f"(hi) : "l"(v));
}
__device__ __forceinline__ void fma2(ull& d, ull a, ull b) {
    asm("fma.rn.f32x2 %0, %1, %2, %0;" : "+l"(d) : "l"(a), "l"(b));
}
__device__ __forceinline__ void comb(float& m, float& s, float m2, float s2) {
    float M = fmaxf(m, m2);
    float S = 0.f;
    if (m  > -INFINITY) S += s  * __expf(m  - M);
    if (m2 > -INFINITY) S += s2 * __expf(m2 - M);
    m = M; s = S;
}

// ---------------- 1) GEMM1 partials: spec[k][i] += U[n][k]*x[n][i] ----------
__global__ void __launch_bounds__(256, 2) k_gemm1(const float* __restrict__ U,
                                                  const float* __restrict__ x) {
    __shared__ float u_s[32][C];
    __shared__ float x_s[32][C];
    int b  = blockIdx.x;
    int n0 = b * CHUNK1;
    int n1 = min(n0 + CHUNK1, N_TOK);
    int tid = threadIdx.x;
    int tx = tid & 15, ty = tid >> 4;

    ull acc[8][4];
    ull z = pack2(0.0f, 0.0f);
#pragma unroll
    for (int i = 0; i < 8; i++)
#pragma unroll
        for (int j = 0; j < 4; j++) acc[i][j] = z;

    for (int nb = n0; nb < n1; nb += 32) {
#pragma unroll
        for (int t4 = 0; t4 < 4; t4++) {
            int f  = t4 * 256 + tid;
            int r  = f >> 5, c4 = f & 31;
            int n  = nb + r;
            float4 vu, vx;
            if (n < n1) {
                vu = ((const float4*)(U + (size_t)n * C))[c4];
                vx = ((const float4*)(x + (size_t)n * C))[c4];
            } else {
                vu = make_float4(0.f, 0.f, 0.f, 0.f);
                vx = vu;
            }
            ((float4*)&u_s[r][0])[c4] = vu;
            ((float4*)&x_s[r][0])[c4] = vx;
        }
        __syncthreads();
#pragma unroll 2
        for (int r = 0; r < 32; ++r) {
            float au[8];
            *(float4*)&au[0] = *(const float4*)&u_s[r][8 * ty];
            *(float4*)&au[4] = *(const float4*)&u_s[r][8 * ty + 4];
            // B fragment split: i = 4tx..4tx+3 and 4tx+64..4tx+67 (conflict-free LDS.128)
            ulonglong2 bl0 = *(const ulonglong2*)&x_s[r][4 * tx];
            ulonglong2 bl1 = *(const ulonglong2*)&x_s[r][4 * tx + 64];
            ull bb[4] = { bl0.x, bl0.y, bl1.x, bl1.y };
#pragma unroll
            for (int ii = 0; ii < 8; ii++) {
                ull a2 = pack2(au[ii], au[ii]);
#pragma unroll
                for (int j = 0; j < 4; j++) fma2(acc[ii][j], a2, bb[j]);
            }
        }
        __syncthreads();
    }

    float* dst = g_part + (size_t)b * (C * C);
#pragma unroll
    for (int ii = 0; ii < 8; ii++) {
        float v[8];
#pragma unroll
        for (int j = 0; j < 4; j++) unpack2(acc[ii][j], v[2 * j], v[2 * j + 1]);
        float* row = dst + (8 * ty + ii) * C;
        *(float4*)&row[4 * tx]      = make_float4(v[0], v[1], v[2], v[3]);
        *(float4*)&row[4 * tx + 64] = make_float4(v[4], v[5], v[6], v[7]);
    }
}

// ---------------- 2) reduce partials -> g_spec ------------------------------
__global__ void k_rsum() {
    int j = blockIdx.x * 256 + threadIdx.x;
    float s0 = 0.f, s1 = 0.f, s2 = 0.f, s3 = 0.f;
    int b = 0;
    for (; b + 4 <= NB1; b += 4) {
        s0 += g_part[(b + 0) * (C * C) + j];
        s1 += g_part[(b + 1) * (C * C) + j];
        s2 += g_part[(b + 2) * (C * C) + j];
        s3 += g_part[(b + 3) * (C * C) + j];
    }
    for (; b < NB1; b++) s0 += g_part[b * (C * C) + j];
    g_spec[j] = (s0 + s1) + (s2 + s3);
}

// ---------------- 3) mixed: one warp per (o, 4 k's) -------------------------
__global__ void __launch_bounds__(256) k_mixed_w(const float* __restrict__ coeffs) {
    int gw   = blockIdx.x * 8 + (threadIdx.x >> 5);   // 0..4095
    int lane = threadIdx.x & 31;
    int o = gw >> 5, k0 = (gw & 31) * 4;
    float s[4];
#pragma unroll
    for (int kk = 0; kk < 4; kk++) {
        int k = k0 + kk;
        float4 a  = ((const float4*)(coeffs + (((size_t)o * C + k) << 7)))[lane];
        float4 bv = ((const float4*)(g_spec + (k << 7)))[lane];
        s[kk] = a.x * bv.x + a.y * bv.y + a.z * bv.z + a.w * bv.w;
    }
#pragma unroll
    for (int off = 16; off; off >>= 1)
#pragma unroll
        for (int kk = 0; kk < 4; kk++)
            s[kk] += __shfl_xor_sync(0xffffffffu, s[kk], off);
    if (lane == 0) {
#pragma unroll
        for (int kk = 0; kk < 4; kk++) g_mixedT[(k0 + kk) * C + o] = s[kk];
    }
}

// ---------------- 4) GEMM2 (128o x 64n tile) + coalesced logits + partials --
// lane l owns o = 4l..4l+3 (packed in FFMA2 pairs); warp w owns n = 8w..8w+7.
__global__ void __launch_bounds__(256, 2) k_gemm3c(const float* __restrict__ U,
                                                   float* __restrict__ out) {
    extern __shared__ float sh[];
    float* m_s = sh;               // [k][o] 128x128 = 64KB
    float* u_s = sh + C * C;       // [n][k]  64x128 = 32KB (raw copy of U tile)
    int b  = blockIdx.x;
    int n0 = b * NT3;
    int tid = threadIdx.x;
    int l = tid & 31, w = tid >> 5;
    int nvalid = min(NT3, N_TOK - n0);

#pragma unroll
    for (int i = 0; i < 16; i++)                 // m tile: 4096 float4
        ((float4*)m_s)[i * 256 + tid] = ((const float4*)g_mixedT)[i * 256 + tid];
#pragma unroll
    for (int i = 0; i < 8; i++) {                // U tile: 2048 float4, coalesced
        int f = i * 256 + tid;
        int r = f >> 5, c4 = f & 31;
        float4 v = make_float4(0.f, 0.f, 0.f, 0.f);
        if (r < nvalid) v = ((const float4*)(U + (size_t)(n0 + r) * C))[c4];
        ((float4*)u_s)[f] = v;
    }
    __syncthreads();

    ull acc[8][2];
    ull z = pack2(0.f, 0.f);
#pragma unroll
    for (int j = 0; j < 8; j++) { acc[j][0] = z; acc[j][1] = z; }

#pragma unroll 2
    for (int k4 = 0; k4 < C; k4 += 4) {
        float4 uv[8];
#pragma unroll
        for (int j = 0; j < 8; j++)              // broadcast reads (all lanes same addr)
            uv[j] = *(const float4*)&u_s[(8 * w + j) * C + k4];
#pragma unroll
        for (int kk = 0; kk < 4; kk++) {
            ulonglong2 mv = *(const ulonglong2*)&m_s[(k4 + kk) * C + 4 * l];
#pragma unroll
            for (int j = 0; j < 8; j++) {
                float u = (kk == 0) ? uv[j].x : (kk == 1) ? uv[j].y
                        : (kk == 2) ? uv[j].z : uv[j].w;
                ull b2 = pack2(u, u);
                fma2(acc[j][0], mv.x, b2);
                fma2(acc[j][1], mv.y, b2);
            }
        }
    }

    // coalesced logit store: warp writes full 128-float rows of out[n][:]
#pragma unroll
    for (int j = 0; j < 8; j++) {
        int n = n0 + 8 * w + j;
        if (n < N_TOK)
            *(ulonglong2*)&out[(size_t)n * C + 4 * l] =
                make_ulonglong2(acc[j][0], acc[j][1]);
    }

    // per-thread softmax partials (4 o's, 8 n's)
    float v[8][4];
#pragma unroll
    for (int j = 0; j < 8; j++) {
        unpack2(acc[j][0], v[j][0], v[j][1]);
        unpack2(acc[j][1], v[j][2], v[j][3]);
    }
    float pm[4], ps[4];
#pragma unroll
    for (int oo = 0; oo < 4; oo++) {
        float m = -INFINITY;
#pragma unroll
        for (int j = 0; j < 8; j++)
            if (8 * w + j < nvalid) m = fmaxf(m, v[j][oo]);
        float s = 0.f;
        if (m > -INFINITY) {
#pragma unroll
            for (int j = 0; j < 8; j++)
                if (8 * w + j < nvalid) s += __expf(v[j][oo] - m);
        }
        pm[oo] = m; ps[oo] = s;
    }

    __syncthreads();                  // safe to reuse u_s
    float* red_m = u_s;               // [o][8]
    float* red_s = u_s + C * 8;
#pragma unroll
    for (int oo = 0; oo < 4; oo++) {
        red_m[(4 * l + oo) * 8 + w] = pm[oo];
        red_s[(4 * l + oo) * 8 + w] = ps[oo];
    }
    __syncthreads();
    if (tid < C) {
        int o = tid;
        float M = -INFINITY, S = 0.f;
#pragma unroll
        for (int ww = 0; ww < 8; ww++)
            comb(M, S, red_m[o * 8 + ww], red_s[o * 8 + ww]);
        g_pm[(size_t)o * NB3 + b] = M;     // [o][b]: coalesced read later
        g_ps[(size_t)o * NB3 + b] = S;
    }
}

// ---------------- 5) combine softmax partials -------------------------------
__global__ void k_softmax_par() {
    int o = blockIdx.x;
    float M = -INFINITY, S = 0.f;
    for (int b = threadIdx.x; b < NB3; b += 256)
        comb(M, S, g_pm[(size_t)o * NB3 + b], g_ps[(size_t)o * NB3 + b]);
#pragma unroll
    for (int off = 16; off; off >>= 1) {
        float m2 = __shfl_xor_sync(0xffffffffu, M, off);
        float s2 = __shfl_xor_sync(0xffffffffu, S, off);
        comb(M, S, m2, s2);
    }
    __shared__ float sm[8], ss[8];
    int wq = threadIdx.x >> 5, lane = threadIdx.x & 31;
    if (lane == 0) { sm[wq] = M; ss[wq] = S; }
    __syncthreads();
    if (threadIdx.x == 0) {
#pragma unroll
        for (int i = 1; i < 8; i++) comb(sm[0], ss[0], sm[i], ss[i]);
        g_max[o]  = sm[0];
        g_sinv[o] = 1.0f / ss[0];
    }
}

// ---------------- 6) final: in-place exp + normalize (2 float4/thread) ------
__global__ void k_final2(float* __restrict__ out) {
    int base = blockIdx.x * 512 + threadIdx.x;
#pragma unroll
    for (int h = 0; h < 2; h++) {
        int f = base + h * 256;                    // float4 index
        float4 v = ((const float4*)out)[f];
        int og = f & 31;
        float4 M = ((const float4*)g_max)[og];
        float4 I = ((const float4*)g_sinv)[og];
        v.x = __expf(v.x - M.x) * I.x;
        v.y = __expf(v.y - M.y) * I.y;
        v.z = __expf(v.z - M.z) * I.z;
        v.w = __expf(v.w - M.w) * I.w;
        ((float4*)out)[f] = v;
    }
}

// ---------------- launcher ---------------------------------------------------
extern "C" void kernel_launch(void* const* d_in, const int* in_sizes, int n_in,
                              void* d_out, int out_size) {
    const float* x      = (const float*)d_in[0];
    const float* U      = (const float*)d_in[1];
    const float* coeffs = (const float*)d_in[2];
    float* out = (float*)d_out;

    int smem3 = (C * C + NT3 * C) * (int)sizeof(float);   // 98304
    cudaFuncSetAttribute(k_gemm3c, cudaFuncAttributeMaxDynamicSharedMemorySize,
                         smem3);

    k_gemm1<<<NB1, 256>>>(U, x);
    k_rsum<<<64, 256>>>();
    k_mixed_w<<<512, 256>>>(coeffs);
    k_gemm3c<<<NB3, 256, smem3>>>(U, out);
    k_softmax_par<<<C, 256>>>();
    k_final2<<<N_TOK * C / 4 / 512, 256>>>(out);
}